// round 6
// baseline (speedup 1.0000x reference)
#include <cuda_runtime.h>
#include <math.h>

#define NB 2048
#define NC 32
#define DD 64
#define AA 8

// exp1[n][m] = -0.25 * sum_d (c_n[d]-c_m[d])^2 / l[d]^2   (batch-independent)
__device__ float g_exp1[NC * NC];

__global__ void prep_kernel(const float* __restrict__ centers,
                            const float* __restrict__ ls) {
    int t = threadIdx.x;           // 1024 threads = 32x32 pairs
    int n = t >> 5, m = t & 31;
    float acc = 0.f;
#pragma unroll
    for (int d = 0; d < DD; ++d) {
        float df = centers[n * DD + d] - centers[m * DD + d];
        float l = ls[d];
        acc += (df * df) / (l * l);
    }
    g_exp1[t] = -0.25f * acc;
}

// Blocked in-place Cholesky, panel width 8. Panel factor by one warp
// (rotating across warps), trailing SYRK by all 256 threads.
__device__ __forceinline__ void cholesky64_blk(float (*A)[DD + 1], int tid) {
    const int lane = tid & 31;
    const int warp = tid >> 5;
    const int ty = tid >> 4, tx = tid & 15;
#pragma unroll 1
    for (int p = 0; p < 8; ++p) {
        const int k0 = p * 8, pe = k0 + 8;
        if (warp == (p & 7)) {
#pragma unroll 1
            for (int j = k0; j < pe; ++j) {
                float d = A[j][j];
                float inv = rsqrtf(d);
                if (lane == 0) A[j][j] = d * inv;      // sqrt(d)
                for (int i = j + 1 + lane; i < DD; i += 32) A[i][j] *= inv;
                __syncwarp();
                float cj[7];
#pragma unroll
                for (int q = 0; q < 7; ++q) {
                    int jj = j + 1 + q;
                    cj[q] = (jj < pe) ? A[jj][j] : 0.f;
                }
                for (int i = j + 1 + lane; i < DD; i += 32) {
                    float a = A[i][j];
#pragma unroll
                    for (int q = 0; q < 7; ++q) {
                        int jj = j + 1 + q;
                        if (jj < pe) A[i][jj] -= a * cj[q];
                    }
                }
                __syncwarp();
            }
        }
        __syncthreads();
        if (pe < DD) {
            for (int i = pe + ty; i < DD; i += 16) {
                float ai[8];
#pragma unroll
                for (int kk = 0; kk < 8; ++kk) ai[kk] = A[i][k0 + kk];
                for (int j = pe + tx; j <= i; j += 16) {
                    float acc = A[i][j];
#pragma unroll
                    for (int kk = 0; kk < 8; ++kk) acc -= ai[kk] * A[j][k0 + kk];
                    A[i][j] = acc;
                }
            }
            __syncthreads();
        }
    }
}

// In-place inversion of lower-triangular L (64x64) held in A (lower+diag).
// Uscratch: >= 3*16*17 floats. Result: A holds Linv (lower+diag), and the
// upper triangle of each 16x16 diagonal block is ZEROED (required by the
// dense block GEMMs below).
__device__ __forceinline__ void invert_lower64(float (*A)[DD + 1],
                                               float* U, int tid) {
    const int lane = tid & 31;
    const int warp = tid >> 5;
    // 1) invert four 16x16 diagonal blocks in place (warps 0-3, warp-sync),
    //    zeroing the upper triangle of each block as we go.
    if (warp < 4) {
        const int b0 = warp * 16;
        const int j = lane;   // column owned (lanes >=16 idle but sync)
#pragma unroll 1
        for (int i = 0; i < 16; ++i) {
            float s = 0.f;
            if (j < i) {
                for (int k = j; k < i; ++k) s += A[b0 + i][b0 + k] * A[b0 + k][b0 + j];
            }
            float di = A[b0 + i][b0 + i];
            __syncwarp();
            if (j < i)            A[b0 + i][b0 + j] = -s / di;
            else if (j == i)      A[b0 + i][b0 + i] = 1.0f / di;
            else if (j < 16)      A[b0 + i][b0 + j] = 0.0f;   // zero upper
            __syncwarp();
        }
    }
    __syncthreads();
    // 2) off-diagonal blocks, block-columns right-to-left (dense 16x16 GEMMs;
    //    diag blocks are now exactly lower-triangular with zeros above)
    const int r = tid >> 4, c = tid & 15;
#pragma unroll 1
    for (int bj = 2; bj >= 0; --bj) {
        const int nb = 3 - bj;
        // U[m] = sum_{bk=bj+1}^{bi} Linv(bi,bk) * L(bk,bj),  bi = bj+1+m
        for (int m = 0; m < nb; ++m) {
            const int bi = bj + 1 + m;
            float acc = 0.f;
            for (int bk = bj + 1; bk <= bi; ++bk) {
#pragma unroll
                for (int kk = 0; kk < 16; ++kk)
                    acc += A[bi * 16 + r][bk * 16 + kk] * A[bk * 16 + kk][bj * 16 + c];
            }
            U[m * 272 + r * 17 + c] = acc;
        }
        __syncthreads();
        // Linv(bi,bj) = -U[m] * Linv(bj,bj)
        for (int m = 0; m < nb; ++m) {
            const int bi = bj + 1 + m;
            float acc = 0.f;
#pragma unroll
            for (int kk = 0; kk < 16; ++kk)
                acc += U[m * 272 + r * 17 + kk] * A[bj * 16 + kk][bj * 16 + c];
            A[bi * 16 + r][bj * 16 + c] = -acc;
        }
        __syncthreads();
    }
}

__global__ __launch_bounds__(256, 4) void rbf_kernel(
    const float* __restrict__ mean, const float* __restrict__ cov,
    const float* __restrict__ centers, const float* __restrict__ weights,
    const float* __restrict__ ls,
    float* __restrict__ out_am, float* __restrict__ out_ac,
    float* __restrict__ out_cc) {
    __shared__ float A[DD][DD + 1];     // matrix -> L -> Linv (both phases)
    __shared__ float X[DD][NC + 1];     // RHS / solutions (D-major)
    __shared__ float Dm[DD][NC + 1];    // d_n = c_n - mean, transposed
    __shared__ float CC[DD][AA];        // cross_cov pre-squash
    __shared__ float G[NC][NC + 1];     // scratch (inversion U) -> Gram -> Q
    __shared__ float W[NC][AA];
    __shared__ float pw[NC][AA];        // phi*W, later P = Q W
    __shared__ float phi[NC];
    __shared__ float smean[DD], sinvl[DD], sl2[DD];
    __shared__ float ldiag[DD];
    __shared__ float s_scal[2];         // [0]=normalizer, [1]=c_q
    __shared__ float s_am[AA], s_dc[AA], s_cd[AA];
    __shared__ float R8[AA][AA + 1];
    __shared__ float ACm[AA][AA + 1];
    __shared__ float gd[NC];

    const int tid = threadIdx.x;
    const int b = blockIdx.x;
    const float* covb = cov + (size_t)b * DD * DD;
    const float* meanb = mean + (size_t)b * DD;
    float* U = &G[0][0];

    if (tid < DD) {
        float l = ls[tid];
        smean[tid] = meanb[tid];
        sinvl[tid] = 1.0f / l;
        sl2[tid] = l * l;
    }
    {
        int n = tid >> 3, a = tid & 7;
        W[n][a] = weights[tid];
    }
    __syncthreads();

    // Dm[d][n] = centers[n][d] - mean[d];  A = diag(invl) cov diag(invl) + I
    for (int idx = tid; idx < NC * DD; idx += 256) {
        int n = idx >> 6, d = idx & 63;
        Dm[d][n] = centers[idx] - smean[d];
    }
    for (int idx = tid; idx < DD * DD; idx += 256) {
        int i = idx >> 6, j = idx & 63;
        float v = covb[idx] * sinvl[i] * sinvl[j];
        if (i == j) v += 1.0f;
        A[i][j] = v;
    }
    __syncthreads();
    for (int idx = tid; idx < DD * NC; idx += 256) {
        int d = idx >> 5, n = idx & 31;
        X[d][n] = Dm[d][n] * sinvl[d];
    }
    __syncthreads();

    cholesky64_blk(A, tid);
    if (tid < DD) ldiag[tid] = logf(A[tid][tid]);
    __syncthreads();
    invert_lower64(A, U, tid);

    // T = Linv^T (Linv S), in place in X with register staging
    {
        const int n = tid & 31, r0 = tid >> 5;
        float yreg[8];
#pragma unroll
        for (int u = 0; u < 8; ++u) {
            const int i = u * 8 + r0;
            float acc = 0.f;
#pragma unroll 8
            for (int k = 0; k <= i; ++k) acc += A[i][k] * X[k][n];
            yreg[u] = acc;
        }
        __syncthreads();
#pragma unroll
        for (int u = 0; u < 8; ++u) X[u * 8 + r0][n] = yreg[u];
        __syncthreads();
#pragma unroll
        for (int u = 0; u < 8; ++u) {
            const int i = u * 8 + r0;
            float acc = 0.f;
#pragma unroll 8
            for (int k = i; k < DD; ++k) acc += A[k][i] * X[k][n];
            yreg[u] = acc;
        }
        __syncthreads();
#pragma unroll
        for (int u = 0; u < 8; ++u) X[u * 8 + r0][n] = yreg[u];
    }

    if (tid == 0) {
        float s = 0.f;
        for (int i = 0; i < DD; ++i) s += ldiag[i];
        s_scal[0] = expf(-s);   // exp(-0.5*logdet)
    }
    __syncthreads();

    // phi[n] = normalizer * exp(-0.5 * sum_d scaled[n][d]*t[n][d])
    if (tid < NC) {
        float acc = 0.f;
        for (int d = 0; d < DD; ++d) acc += Dm[d][tid] * sinvl[d] * X[d][tid];
        phi[tid] = expf(-0.5f * acc) * s_scal[0];
    }
    __syncthreads();
    {
        int n = tid >> 3, a = tid & 7;
        pw[n][a] = phi[n] * W[n][a];
    }
    __syncthreads();
    if (tid < AA) {
        float s = 0.f;
        for (int n = 0; n < NC; ++n) s += pw[n][tid];
        s_am[tid] = s;
    }
    // cross_cov[d][a] = invl[d] * sum_n t^T[d][n] * (phi W)[n][a]
    for (int idx = tid; idx < DD * AA; idx += 256) {
        int d = idx >> 3, a = idx & 7;
        float acc = 0.f;
#pragma unroll 8
        for (int n = 0; n < NC; ++n) acc += X[d][n] * pw[n][a];
        CC[d][a] = acc * sinvl[d];
    }
    __syncthreads();

    // ---- Phase 2: B_q = cov + diag(l^2/2) ----
    for (int idx = tid; idx < DD * DD; idx += 256) {
        int i = idx >> 6, j = idx & 63;
        float v = covb[idx];
        if (i == j) v += 0.5f * sl2[i];
        A[i][j] = v;
    }
    for (int idx = tid; idx < DD * NC; idx += 256) {
        int d = idx >> 5, n = idx & 31;
        X[d][n] = Dm[d][n];
    }
    __syncthreads();
    cholesky64_blk(A, tid);
    if (tid < DD) ldiag[tid] = 0.5f * logf(0.5f * sl2[tid]) - logf(A[tid][tid]);
    __syncthreads();
    invert_lower64(A, U, tid);

    // Y = Linv_q * D  (forward triangular multiply), in place in X
    {
        const int n = tid & 31, r0 = tid >> 5;
        float yreg[8];
#pragma unroll
        for (int u = 0; u < 8; ++u) {
            const int i = u * 8 + r0;
            float acc = 0.f;
#pragma unroll 8
            for (int k = 0; k <= i; ++k) acc += A[i][k] * X[k][n];
            yreg[u] = acc;
        }
        __syncthreads();
#pragma unroll
        for (int u = 0; u < 8; ++u) X[u * 8 + r0][n] = yreg[u];
    }
    if (tid == 0) {
        float s = 0.f;
        for (int i = 0; i < DD; ++i) s += ldiag[i];
        s_scal[1] = expf(s);    // c_q
    }
    __syncthreads();

    // G = Y^T Y  (32x32)
    for (int p = tid; p < NC * NC; p += 256) {
        int n = p >> 5, m = p & 31;
        float acc = 0.f;
#pragma unroll 8
        for (int d = 0; d < DD; ++d) acc += X[d][n] * X[d][m];
        G[n][m] = acc;
    }
    __syncthreads();
    if (tid < NC) gd[tid] = G[tid][tid];
    __syncthreads();
    // Q[n][m] = c_q * exp(exp1 - (G_nn + 2 G_nm + G_mm)/8)
    {
        float cq = s_scal[1];
        for (int p = tid; p < NC * NC; p += 256) {
            int n = p >> 5, m = p & 31;
            G[n][m] = cq * expf(g_exp1[p] - 0.125f * (gd[n] + 2.0f * G[n][m] + gd[m]));
        }
    }
    __syncthreads();
    // P = Q W
    {
        int n = tid >> 3, c = tid & 7;
        float acc = 0.f;
#pragma unroll 8
        for (int m = 0; m < NC; ++m) acc += G[n][m] * W[m][c];
        pw[n][c] = acc;
    }
    __syncthreads();
    // R = W^T P (8x8)
    if (tid < AA * AA) {
        int a = tid >> 3, c = tid & 7;
        float acc = 0.f;
        for (int n = 0; n < NC; ++n) acc += W[n][a] * pw[n][c];
        R8[a][c] = acc;
    }
    __syncthreads();
    if (tid < AA * AA) {
        int a = tid >> 3, c = tid & 7;
        float v = 0.5f * (R8[a][c] + R8[c][a]) - s_am[a] * s_am[c];
        if (a == c) v += 1e-6f;
        ACm[a][c] = v;
    }
    __syncthreads();

    // ---- squash_sin (max_action = 1) ----
    if (tid < AA) {
        float dc = ACm[tid][tid];
        float e = expf(-0.5f * dc);
        s_dc[tid] = dc;
        s_cd[tid] = e * cosf(s_am[tid]);           // diag of C
        out_am[(size_t)b * AA + tid] = e * sinf(s_am[tid]);
    }
    __syncthreads();
    if (tid < AA * AA) {
        int a = tid >> 3, c = tid & 7;
        float lq = -0.5f * (s_dc[a] + s_dc[c]);
        float q = expf(lq);
        float v = ACm[a][c];
        float sq = 0.5f * ((expf(lq + v) - q) * cosf(s_am[a] - s_am[c])
                         - (expf(lq - v) - q) * cosf(s_am[a] + s_am[c]));
        out_ac[(size_t)b * AA * AA + tid] = sq;
    }
    for (int idx = tid; idx < DD * AA; idx += 256) {
        int c = idx & 7;
        out_cc[(size_t)b * DD * AA + idx] = CC[idx >> 3][c] * s_cd[c];
    }
}

extern "C" void kernel_launch(void* const* d_in, const int* in_sizes, int n_in,
                              void* d_out, int out_size) {
    const float* mean = (const float*)d_in[0];
    const float* cov = (const float*)d_in[1];
    const float* centers = (const float*)d_in[2];
    const float* weights = (const float*)d_in[3];
    const float* ls = (const float*)d_in[4];
    float* out = (float*)d_out;

    int B = in_sizes[0] / DD;   // 2048
    float* out_am = out;
    float* out_ac = out + (size_t)B * AA;
    float* out_cc = out + (size_t)B * AA + (size_t)B * AA * AA;

    prep_kernel<<<1, 1024>>>(centers, ls);
    rbf_kernel<<<B, 256>>>(mean, cov, centers, weights, ls, out_am, out_ac, out_cc);
}

// round 12
// speedup vs baseline: 1.6686x; 1.6686x over previous
#include <cuda_runtime.h>
#include <math.h>

#define NB 2048
#define NC 32
#define DD 64
#define AA 8

// exp1[n][m] = -0.25 * sum_d (c_n[d]-c_m[d])^2 / l[d]^2   (batch-independent)
__device__ float g_exp1[NC * NC];

__global__ void prep_kernel(const float* __restrict__ centers,
                            const float* __restrict__ ls) {
    int t = threadIdx.x;           // 1024 threads = 32x32 pairs
    int n = t >> 5, m = t & 31;
    float acc = 0.f;
#pragma unroll
    for (int d = 0; d < DD; ++d) {
        float df = centers[n * DD + d] - centers[m * DD + d];
        float l = ls[d];
        acc += (df * df) / (l * l);
    }
    g_exp1[t] = -0.25f * acc;
}

// Blocked in-place Cholesky, panel width 8. Panel factor by one warp
// (rotating across warps), trailing SYRK by all 256 threads.
__device__ __forceinline__ void cholesky64_blk(float (*A)[DD + 1], int tid) {
    const int lane = tid & 31;
    const int warp = tid >> 5;
    const int ty = tid >> 4, tx = tid & 15;
#pragma unroll 1
    for (int p = 0; p < 8; ++p) {
        const int k0 = p * 8, pe = k0 + 8;
        if (warp == (p & 7)) {
#pragma unroll 1
            for (int j = k0; j < pe; ++j) {
                float d = A[j][j];
                float inv = rsqrtf(d);
                if (lane == 0) A[j][j] = d * inv;      // sqrt(d)
                for (int i = j + 1 + lane; i < DD; i += 32) A[i][j] *= inv;
                __syncwarp();
                float cj[7];
#pragma unroll
                for (int q = 0; q < 7; ++q) {
                    int jj = j + 1 + q;
                    cj[q] = (jj < pe) ? A[jj][j] : 0.f;
                }
                for (int i = j + 1 + lane; i < DD; i += 32) {
                    float a = A[i][j];
#pragma unroll
                    for (int q = 0; q < 7; ++q) {
                        int jj = j + 1 + q;
                        if (jj < pe) A[i][jj] -= a * cj[q];
                    }
                }
                __syncwarp();
            }
        }
        __syncthreads();
        if (pe < DD) {
            for (int i = pe + ty; i < DD; i += 16) {
                float ai[8];
#pragma unroll
                for (int kk = 0; kk < 8; ++kk) ai[kk] = A[i][k0 + kk];
                for (int j = pe + tx; j <= i; j += 16) {
                    float acc = A[i][j];
#pragma unroll
                    for (int kk = 0; kk < 8; ++kk) acc -= ai[kk] * A[j][k0 + kk];
                    A[i][j] = acc;
                }
            }
            __syncthreads();
        }
    }
}

// In-place inversion of lower-triangular L (64x64) held in A (lower+diag).
// Uscratch: >= 3*16*17 floats. Result: A holds Linv (lower+diag), and the
// upper triangle of each 16x16 diagonal block is ZEROED.
__device__ __forceinline__ void invert_lower64(float (*A)[DD + 1],
                                               float* U, int tid) {
    const int lane = tid & 31;
    const int warp = tid >> 5;
    if (warp < 4) {
        const int b0 = warp * 16;
        const int j = lane;
#pragma unroll 1
        for (int i = 0; i < 16; ++i) {
            float s = 0.f;
            if (j < i) {
                for (int k = j; k < i; ++k) s += A[b0 + i][b0 + k] * A[b0 + k][b0 + j];
            }
            float di = A[b0 + i][b0 + i];
            __syncwarp();
            if (j < i)            A[b0 + i][b0 + j] = -s / di;
            else if (j == i)      A[b0 + i][b0 + i] = 1.0f / di;
            else if (j < 16)      A[b0 + i][b0 + j] = 0.0f;   // zero upper
            __syncwarp();
        }
    }
    __syncthreads();
    const int r = tid >> 4, c = tid & 15;
#pragma unroll 1
    for (int bj = 2; bj >= 0; --bj) {
        const int nb = 3 - bj;
        for (int m = 0; m < nb; ++m) {
            const int bi = bj + 1 + m;
            float acc = 0.f;
            for (int bk = bj + 1; bk <= bi; ++bk) {
#pragma unroll
                for (int kk = 0; kk < 16; ++kk)
                    acc += A[bi * 16 + r][bk * 16 + kk] * A[bk * 16 + kk][bj * 16 + c];
            }
            U[m * 272 + r * 17 + c] = acc;
        }
        __syncthreads();
        for (int m = 0; m < nb; ++m) {
            const int bi = bj + 1 + m;
            float acc = 0.f;
#pragma unroll
            for (int kk = 0; kk < 16; ++kk)
                acc += U[m * 272 + r * 17 + kk] * A[bj * 16 + kk][bj * 16 + c];
            A[bi * 16 + r][bj * 16 + c] = -acc;
        }
        __syncthreads();
    }
}

__global__ __launch_bounds__(256, 4) void rbf_kernel(
    const float* __restrict__ mean, const float* __restrict__ cov,
    const float* __restrict__ centers, const float* __restrict__ weights,
    const float* __restrict__ ls,
    float* __restrict__ out_am, float* __restrict__ out_ac,
    float* __restrict__ out_cc) {
    __shared__ float A[DD][DD + 1];     // matrix -> L -> Linv (both phases)
    __shared__ float X[DD][NC + 1];     // RHS / solutions (D-major)
    __shared__ float CC[DD][AA];        // cross_cov pre-squash
    __shared__ float G[NC][NC + 1];     // scratch (inversion U) -> Gram -> Q
    __shared__ float W[NC][AA];
    __shared__ float pw[NC][AA];        // phi*W, later P = Q W
    __shared__ float phi[NC];
    __shared__ float cp[8][NC];         // column-norm partials
    __shared__ float smean[DD], sinvl[DD], sl2[DD];
    __shared__ float ldiag[DD];
    __shared__ float s_scal[2];         // [0]=normalizer, [1]=c_q
    __shared__ float s_am[AA], s_dc[AA], s_cd[AA];
    __shared__ float R8[AA][AA + 1];
    __shared__ float ACm[AA][AA + 1];
    __shared__ float gd[NC];

    const int tid = threadIdx.x;
    const int b = blockIdx.x;
    const float* covb = cov + (size_t)b * DD * DD;
    const float* meanb = mean + (size_t)b * DD;
    float* U = &G[0][0];
    const int n = tid & 31, r0 = tid >> 5;   // apply-phase mapping

    if (tid < DD) {
        float l = ls[tid];
        smean[tid] = meanb[tid];
        sinvl[tid] = 1.0f / l;
        sl2[tid] = l * l;
    }
    {
        int nn = tid >> 3, a = tid & 7;
        W[nn][a] = weights[tid];
    }
    __syncthreads();

    // A = diag(invl) cov diag(invl) + I ; X[d][n] = (c_n[d]-mean[d])*invl[d]
    for (int idx = tid; idx < DD * DD; idx += 256) {
        int i = idx >> 6, j = idx & 63;
        float v = covb[idx] * sinvl[i] * sinvl[j];
        if (i == j) v += 1.0f;
        A[i][j] = v;
    }
    for (int idx = tid; idx < NC * DD; idx += 256) {
        int nn = idx >> 6, d = idx & 63;
        X[d][nn] = (centers[idx] - smean[d]) * sinvl[d];
    }
    __syncthreads();

    cholesky64_blk(A, tid);
    if (tid < DD) ldiag[tid] = logf(A[tid][tid]);
    __syncthreads();
    invert_lower64(A, U, tid);

    // Y1 = Linv * S  (k-outer, A[i][k] warp-broadcast), colnorms -> cp
    {
        float y[8];
#pragma unroll
        for (int u = 0; u < 8; ++u) y[u] = 0.f;
        for (int k = 0; k < DD; ++k) {
            float xk = X[k][n];
#pragma unroll
            for (int u = 0; u < 8; ++u) {
                int i = u * 8 + r0;
                if (i >= k) y[u] += A[i][k] * xk;
            }
        }
        float pn = 0.f;
#pragma unroll
        for (int u = 0; u < 8; ++u) pn += y[u] * y[u];
        cp[r0][n] = pn;
        __syncthreads();                   // all reads of X done
#pragma unroll
        for (int u = 0; u < 8; ++u) X[u * 8 + r0][n] = y[u];
        __syncthreads();
        // T = Linv^T * Y1
#pragma unroll
        for (int u = 0; u < 8; ++u) y[u] = 0.f;
        for (int k = 0; k < DD; ++k) {
            float xk = X[k][n];
#pragma unroll
            for (int u = 0; u < 8; ++u) {
                int i = u * 8 + r0;
                if (k >= i) y[u] += A[k][i] * xk;
            }
        }
        __syncthreads();
#pragma unroll
        for (int u = 0; u < 8; ++u) X[u * 8 + r0][n] = y[u];
    }

    if (tid == 0) {
        float s = 0.f;
        for (int i = 0; i < DD; ++i) s += ldiag[i];
        s_scal[0] = expf(-s);   // exp(-0.5*logdet)
    }
    __syncthreads();

    // phi[n] = normalizer * exp(-0.5 * |Y1 col n|^2)   (accurate expf: tiny values)
    if (tid < NC) {
        float acc = 0.f;
#pragma unroll
        for (int u = 0; u < 8; ++u) acc += cp[u][tid];
        phi[tid] = expf(-0.5f * acc) * s_scal[0];
    }
    __syncthreads();
    {
        int nn = tid >> 3, a = tid & 7;
        pw[nn][a] = phi[nn] * W[nn][a];
    }
    __syncthreads();
    if (tid < AA) {
        float s = 0.f;
        for (int nn = 0; nn < NC; ++nn) s += pw[nn][tid];
        s_am[tid] = s;
    }
    // cross_cov[d][a] = invl[d] * sum_n t^T[d][n] * (phi W)[n][a]
    for (int idx = tid; idx < DD * AA; idx += 256) {
        int d = idx >> 3, a = idx & 7;
        float acc = 0.f;
#pragma unroll 8
        for (int nn = 0; nn < NC; ++nn) acc += X[d][nn] * pw[nn][a];
        CC[d][a] = acc * sinvl[d];
    }
    __syncthreads();

    // ---- Phase 2: B_q = cov + diag(l^2/2) ----
    for (int idx = tid; idx < DD * DD; idx += 256) {
        int i = idx >> 6, j = idx & 63;
        float v = covb[idx];
        if (i == j) v += 0.5f * sl2[i];
        A[i][j] = v;
    }
    for (int idx = tid; idx < NC * DD; idx += 256) {
        int nn = idx >> 6, d = idx & 63;
        X[d][nn] = centers[idx] - smean[d];
    }
    __syncthreads();
    cholesky64_blk(A, tid);
    if (tid < DD) ldiag[tid] = 0.5f * logf(0.5f * sl2[tid]) - logf(A[tid][tid]);
    __syncthreads();
    invert_lower64(A, U, tid);

    // Y = Linv_q * D (k-outer)
    {
        float y[8];
#pragma unroll
        for (int u = 0; u < 8; ++u) y[u] = 0.f;
        for (int k = 0; k < DD; ++k) {
            float xk = X[k][n];
#pragma unroll
            for (int u = 0; u < 8; ++u) {
                int i = u * 8 + r0;
                if (i >= k) y[u] += A[i][k] * xk;
            }
        }
        __syncthreads();
#pragma unroll
        for (int u = 0; u < 8; ++u) X[u * 8 + r0][n] = y[u];
    }
    if (tid == 0) {
        float s = 0.f;
        for (int i = 0; i < DD; ++i) s += ldiag[i];
        s_scal[1] = expf(s);    // c_q
    }
    __syncthreads();

    // G = Y^T Y  (32x32), 2x2 register tile per thread
    {
        const int n2 = tid >> 4, m2 = tid & 15;
        const int n0 = 2 * n2, m0 = 2 * m2;
        float g00 = 0.f, g01 = 0.f, g10 = 0.f, g11 = 0.f;
        for (int d = 0; d < DD; ++d) {
            float a0 = X[d][n0], a1 = X[d][n0 + 1];
            float b0 = X[d][m0], b1 = X[d][m0 + 1];
            g00 += a0 * b0; g01 += a0 * b1;
            g10 += a1 * b0; g11 += a1 * b1;
        }
        G[n0][m0] = g00; G[n0][m0 + 1] = g01;
        G[n0 + 1][m0] = g10; G[n0 + 1][m0 + 1] = g11;
    }
    __syncthreads();
    if (tid < NC) gd[tid] = G[tid][tid];
    __syncthreads();
    // Q[n][m] = c_q * exp(exp1 - (G_nn + 2 G_nm + G_mm)/8)   (hot: __expf ok, args ~ -50)
    {
        float cq = s_scal[1];
        for (int p = tid; p < NC * NC; p += 256) {
            int nn = p >> 5, m = p & 31;
            G[nn][m] = cq * __expf(g_exp1[p] - 0.125f * (gd[nn] + 2.0f * G[nn][m] + gd[m]));
        }
    }
    __syncthreads();
    // P = Q W
    {
        int nn = tid >> 3, c = tid & 7;
        float acc = 0.f;
#pragma unroll 8
        for (int m = 0; m < NC; ++m) acc += G[nn][m] * W[m][c];
        pw[nn][c] = acc;
    }
    __syncthreads();
    // R = W^T P (8x8)
    if (tid < AA * AA) {
        int a = tid >> 3, c = tid & 7;
        float acc = 0.f;
        for (int nn = 0; nn < NC; ++nn) acc += W[nn][a] * pw[nn][c];
        R8[a][c] = acc;
    }
    __syncthreads();
    if (tid < AA * AA) {
        int a = tid >> 3, c = tid & 7;
        float v = 0.5f * (R8[a][c] + R8[c][a]) - s_am[a] * s_am[c];
        if (a == c) v += 1e-6f;
        ACm[a][c] = v;
    }
    __syncthreads();

    // ---- squash_sin (max_action = 1) ---- accurate libm: values can be ~1e-15,
    // sin.approx flushes tiny args to 0 (caused exact rel_err=1.0 in R7/R10).
    if (tid < AA) {
        float dc = ACm[tid][tid];
        float e = expf(-0.5f * dc);
        s_dc[tid] = dc;
        s_cd[tid] = e * cosf(s_am[tid]);           // diag of C
        out_am[(size_t)b * AA + tid] = e * sinf(s_am[tid]);
    }
    __syncthreads();
    if (tid < AA * AA) {
        int a = tid >> 3, c = tid & 7;
        float lq = -0.5f * (s_dc[a] + s_dc[c]);
        float q = expf(lq);
        float v = ACm[a][c];
        float sq = 0.5f * ((expf(lq + v) - q) * cosf(s_am[a] - s_am[c])
                         - (expf(lq - v) - q) * cosf(s_am[a] + s_am[c]));
        out_ac[(size_t)b * AA * AA + tid] = sq;
    }
    for (int idx = tid; idx < DD * AA; idx += 256) {
        int c = idx & 7;
        out_cc[(size_t)b * DD * AA + idx] = CC[idx >> 3][c] * s_cd[c];
    }
}

extern "C" void kernel_launch(void* const* d_in, const int* in_sizes, int n_in,
                              void* d_out, int out_size) {
    const float* mean = (const float*)d_in[0];
    const float* cov = (const float*)d_in[1];
    const float* centers = (const float*)d_in[2];
    const float* weights = (const float*)d_in[3];
    const float* ls = (const float*)d_in[4];
    float* out = (float*)d_out;

    int B = in_sizes[0] / DD;   // 2048
    float* out_am = out;
    float* out_ac = out + (size_t)B * AA;
    float* out_cc = out + (size_t)B * AA + (size_t)B * AA * AA;

    prep_kernel<<<1, 1024>>>(centers, ls);
    rbf_kernel<<<B, 256>>>(mean, cov, centers, weights, ls, out_am, out_ac, out_cc);
}